// round 6
// baseline (speedup 1.0000x reference)
#include <cuda_runtime.h>

#define B_   8
#define C_   192
#define CQ   32
#define N_   16384
#define NPIX (B_ * N_)
#define EPSF 1e-6f

typedef unsigned long long u64;

// ---------------- scratch ---------------------------------------------------
__device__ float g_Qn[(size_t)NPIX * CQ];   // [px][32] normalized Q
__device__ float g_Kn[(size_t)NPIX * CQ];   // [px][32] normalized K
__device__ float g_G[B_ * 33 * C_];         // rows 0..31: G[m][k]; row 32: xsum[k]
__device__ float g_KS[B_ * CQ];             // sum_n Kn
__device__ float g_M[B_ * 33 * C_];         // rows 0..31: matrix[m][c]; row 32: value_sum[c]

// ---------------- helpers ----------------------------------------------------
__device__ __forceinline__ u64 pack2(float lo, float hi) {
    u64 r;
    asm("mov.b64 %0, {%1, %2};" : "=l"(r)
        : "r"(__float_as_uint(lo)), "r"(__float_as_uint(hi)));
    return r;
}
__device__ __forceinline__ void unpack2(u64 v, float& lo, float& hi) {
    unsigned a, b;
    asm("mov.b64 {%0, %1}, %2;" : "=r"(a), "=r"(b) : "l"(v));
    lo = __uint_as_float(a); hi = __uint_as_float(b);
}
__device__ __forceinline__ void fma2(u64& d, u64 a, u64 b) {
    asm("fma.rn.f32x2 %0, %1, %2, %0;" : "+l"(d) : "l"(a), "l"(b));
}
__device__ __forceinline__ void red2(float* p, float lo, float hi) {
    asm volatile("red.global.add.v2.f32 [%0], {%1, %2};"
                 :: "l"(p), "f"(lo), "f"(hi) : "memory");
}
// 16B shared load returned as two register-paired u64 (no pack MOVs)
__device__ __forceinline__ void lds2(u64& a, u64& b, const float* p) {
    asm volatile("ld.shared.v2.u64 {%0, %1}, [%2];"
                 : "=l"(a), "=l"(b) : "l"(__cvta_generic_to_shared(p)));
}
__device__ __forceinline__ void cpa4(const float* dst, const float* src) {
    asm volatile("cp.async.ca.shared.global [%0], [%1], 4;"
                 :: "l"(__cvta_generic_to_shared(dst)), "l"(src));
}
__device__ __forceinline__ void cpa16(const float* dst, const void* src) {
    asm volatile("cp.async.cg.shared.global [%0], [%1], 16;"
                 :: "l"(__cvta_generic_to_shared(dst)), "l"(src));
}
__device__ __forceinline__ void cpa_commit() { asm volatile("cp.async.commit_group;"); }
__device__ __forceinline__ void cpa_wait0()  { asm volatile("cp.async.wait_group 0;" ::: "memory"); }

// ---------------- K1: Q/K projection + L2 norm (also zeroes G/KS) ------------
// 1024 blocks (8b x 128 slices of 128 px), 256 threads, 2 blocks/SM.
// Thread: 2 px x 8 out-pairs. Register-prefetch of the next 16-k x chunk.
__global__ void __launch_bounds__(256, 2) k_qk(
    const float* __restrict__ x1,
    const float* __restrict__ Wq, const float* __restrict__ bq,
    const float* __restrict__ Wk, const float* __restrict__ bk)
{
    extern __shared__ float sm[];
    float*  sW = sm;                       // 192 rows * 40 float2 = 61440B = 15360 f
    float*  sX = sm + 15360;               // [16][128]  8192B   (total 69632B)

    int tid = threadIdx.x;
    int col = tid & 3, row = tid >> 2;
    int b   = blockIdx.x >> 7;
    int n0  = (blockIdx.x & 127) << 7;
    const float* xb = x1 + (size_t)b * C_ * N_ + n0;

    // zero accumulators for k_gmat
    {
        int z = blockIdx.x * 256 + tid;
        if (z < B_ * 33 * C_) g_G[z] = 0.0f;
        int zk = z - B_ * 33 * C_;
        if (zk >= 0 && zk < B_ * CQ) g_KS[zk] = 0.0f;
    }

    // stage weights: pair o (0..31) of [Q|K]; float2 at k*40+col*10+q*2+e
    for (int i = tid; i < 32 * C_; i += 256) {
        int o = i / C_, k = i % C_;
        int c0 = o >> 3, jj = o & 7, q = jj >> 1, e = jj & 1;
        float lo, hi;
        if (o < 16) { lo = Wq[(2 * o) * C_ + k];           hi = Wq[(2 * o + 1) * C_ + k]; }
        else { int oo = o - 16; lo = Wk[(2 * oo) * C_ + k]; hi = Wk[(2 * oo + 1) * C_ + k]; }
        ((float2*)sW)[k * 40 + c0 * 10 + q * 2 + e] = make_float2(lo, hi);
    }

    u64 acc[2][8];
#pragma unroll
    for (int jj = 0; jj < 8; jj++) {
        int o = col * 8 + jj;
        float lo, hi;
        if (o < 16) { lo = bq[2 * o]; hi = bq[2 * o + 1]; }
        else        { lo = bk[2 * (o - 16)]; hi = bk[2 * (o - 16) + 1]; }
        acc[0][jj] = pack2(lo, hi);
        acc[1][jj] = acc[0][jj];
    }

    // initial chunk
#pragma unroll
    for (int i = 0; i < 8; i++) {
        int idx = i * 256 + tid, t = idx >> 7, px = idx & 127;
        sX[t * 128 + px] = xb[(size_t)t * N_ + px];
    }
    __syncthreads();

    const float4* sW4 = (const float4*)sW;
    for (int ks = 0; ks < C_; ks += 16) {
        float xr[8];
        bool more = (ks + 16) < C_;
        if (more) {
#pragma unroll
            for (int i = 0; i < 8; i++) {
                int idx = i * 256 + tid, t = idx >> 7, px = idx & 127;
                xr[i] = xb[(size_t)(ks + 16 + t) * N_ + px];
            }
        }
#pragma unroll
        for (int t = 0; t < 16; t++) {
            float xv0 = sX[t * 128 + row];
            float xv1 = sX[t * 128 + row + 64];
            u64 x20 = pack2(xv0, xv0);
            u64 x21 = pack2(xv1, xv1);
            int base = (ks + t) * 20 + col * 5;
#pragma unroll
            for (int q = 0; q < 4; q++) {
                float4 w4 = sW4[base + q];
                u64 wa = pack2(w4.x, w4.y);
                u64 wb = pack2(w4.z, w4.w);
                fma2(acc[0][2 * q],     wa, x20);
                fma2(acc[0][2 * q + 1], wb, x20);
                fma2(acc[1][2 * q],     wa, x21);
                fma2(acc[1][2 * q + 1], wb, x21);
            }
        }
        __syncthreads();
        if (more) {
#pragma unroll
            for (int i = 0; i < 8; i++) {
                int idx = i * 256 + tid, t = idx >> 7, px = idx & 127;
                sX[t * 128 + px] = xr[i];
            }
            __syncthreads();
        }
    }

    // epilogue: unpack, L2 normalize (halves joined via shfl_xor 1)
    float v[2][16], s[2];
#pragma unroll
    for (int i = 0; i < 2; i++) {
        s[i] = 0.f;
#pragma unroll
        for (int jj = 0; jj < 8; jj++) {
            unpack2(acc[i][jj], v[i][2 * jj], v[i][2 * jj + 1]);
            s[i] += v[i][2 * jj] * v[i][2 * jj] + v[i][2 * jj + 1] * v[i][2 * jj + 1];
        }
    }
#pragma unroll
    for (int i = 0; i < 2; i++) {
        s[i] += __shfl_xor_sync(0xffffffffu, s[i], 1);
        float r = rsqrtf(s[i]);
#pragma unroll
        for (int t = 0; t < 16; t++) v[i][t] *= r;
    }

    float* dst = (col < 2) ? g_Qn : g_Kn;
    int half = (col & 1) << 4;
    int pxb = b * N_ + n0 + row;
#pragma unroll
    for (int i = 0; i < 2; i++) {
        float4* o4 = (float4*)(dst + (size_t)(pxb + 64 * i) * CQ + half);
#pragma unroll
        for (int jj = 0; jj < 4; jj++)
            o4[jj] = make_float4(v[i][4 * jj], v[i][4 * jj + 1],
                                 v[i][4 * jj + 2], v[i][4 * jj + 3]);
    }
}

// ---------------- K2: G = Kn @ x^T  (+ xsum, + KSum), cp.async double-buffer --
__global__ void __launch_bounds__(256, 2) k_gmat(const float* __restrict__ x)
{
    extern __shared__ float smg[];
    float* sXTb0 = smg;                    // [32][194]
    float* sXTb1 = smg + 6208;
    float* sKnb0 = smg + 12416;            // [32][32]
    float* sKnb1 = smg + 12416 + 1024;

    int tid = threadIdx.x;
    int w = tid >> 5, p = tid & 31;
    int mg = tid & 7, cg = tid >> 3;
    int b  = blockIdx.x >> 6;
    int n0 = (blockIdx.x & 63) << 8;

    const float* xb = x + (size_t)b * C_ * N_ + n0;
    const float4* knb = (const float4*)(g_Kn + ((size_t)b * N_ + n0) * CQ);

    // prefetch tile 0
    {
#pragma unroll
        for (int j = 0; j < 24; j++) {
            int c = w * 24 + j;
            cpa4(sXTb0 + p * 194 + c, xb + (size_t)c * N_ + p);
        }
        cpa16(sKnb0 + tid * 4, knb + tid);
        cpa_commit();
    }

    u64 acc[4][3];
#pragma unroll
    for (int mi = 0; mi < 4; mi++)
#pragma unroll
        for (int j = 0; j < 3; j++) acc[mi][j] = 0ULL;
    float xs[24];
#pragma unroll
    for (int j = 0; j < 24; j++) xs[j] = 0.f;
    float ksacc = 0.f;

    cpa_wait0();
    __syncthreads();

    for (int s = 0; s < 8; s++) {
        if (s < 7) {
            float* nXT = (s & 1) ? sXTb0 : sXTb1;   // buffer (s+1)&1
            float* nKn = (s & 1) ? sKnb0 : sKnb1;
#pragma unroll
            for (int j = 0; j < 24; j++) {
                int c = w * 24 + j;
                cpa4(nXT + p * 194 + c, xb + (size_t)c * N_ + (s + 1) * 32 + p);
            }
            cpa16(nKn + tid * 4, knb + (s + 1) * 256 + tid);
            cpa_commit();
        }
        const float* sXT = (s & 1) ? sXTb1 : sXTb0;
        const float* sKn = (s & 1) ? sKnb1 : sKnb0;

        // xsum partials (read back from the staged tile)
#pragma unroll
        for (int j = 0; j < 24; j++) xs[j] += sXT[p * 194 + w * 24 + j];
        // KSum partials
        if (tid < 32) {
#pragma unroll
            for (int pp = 0; pp < 32; pp++) ksacc += sKn[pp * 32 + tid];
        }

#pragma unroll 4
        for (int pp = 0; pp < 32; pp++) {
            float4 kv = *(const float4*)&sKn[pp * 32 + mg * 4];
            u64 k2a = pack2(kv.x, kv.x), k2b = pack2(kv.y, kv.y);
            u64 k2c = pack2(kv.z, kv.z), k2d = pack2(kv.w, kv.w);
#pragma unroll
            for (int j = 0; j < 3; j++) {
                u64 xv2 = *(const u64*)&sXT[pp * 194 + 2 * (cg + 32 * j)];
                fma2(acc[0][j], k2a, xv2);
                fma2(acc[1][j], k2b, xv2);
                fma2(acc[2][j], k2c, xv2);
                fma2(acc[3][j], k2d, xv2);
            }
        }
        if (s < 7) { cpa_wait0(); __syncthreads(); }
    }

    float* gb = g_G + b * 33 * C_;
#pragma unroll
    for (int mi = 0; mi < 4; mi++)
#pragma unroll
        for (int j = 0; j < 3; j++) {
            float lo, hi; unpack2(acc[mi][j], lo, hi);
            red2(gb + (mg * 4 + mi) * C_ + 2 * (cg + 32 * j), lo, hi);
        }
#pragma unroll
    for (int j = 0; j < 24; j++) {
        float vv = xs[j];
        vv += __shfl_xor_sync(0xffffffffu, vv, 16);
        vv += __shfl_xor_sync(0xffffffffu, vv, 8);
        vv += __shfl_xor_sync(0xffffffffu, vv, 4);
        vv += __shfl_xor_sync(0xffffffffu, vv, 2);
        vv += __shfl_xor_sync(0xffffffffu, vv, 1);
        if (p == 0) atomicAdd(gb + 32 * C_ + w * 24 + j, vv);
    }
    if (tid < 32) atomicAdd(&g_KS[b * CQ + tid], ksacc);
}

// ---------------- K3: M' = Ghat @ Wv^T + outer(coef, bv) ---------------------
__global__ void __launch_bounds__(128) k_small(
    const float* __restrict__ Wv, const float* __restrict__ bv)
{
    extern __shared__ float sm[];
    float* sG  = sm;                  // [33][192]
    float* sWv = sm + 33 * C_;        // [32][193]
    int tid = threadIdx.x;
    int b  = blockIdx.x / 6;
    int ct = blockIdx.x % 6;
    int cl = tid & 31, mg = tid >> 5;
    int c  = ct * 32 + cl;

    for (int i = tid; i < 33 * C_; i += 128) sG[i] = g_G[b * 33 * C_ + i];
    for (int i = tid; i < 32 * C_; i += 128) {
        int cc = i / C_, k = i % C_;
        sWv[cc * 193 + k] = Wv[(size_t)(ct * 32 + cc) * C_ + k];
    }
    __syncthreads();

    float bvc = bv[c];
    float a[9];
#pragma unroll
    for (int rr = 0; rr < 8; rr++) a[rr] = g_KS[b * CQ + mg * 8 + rr] * bvc;
    a[8] = (float)N_ * bvc;

    const float* wp = sWv + cl * 193;
    for (int k = 0; k < C_; k += 2) {
        float w0 = wp[k], w1 = wp[k + 1];
#pragma unroll
        for (int rr = 0; rr < 8; rr++) {
            int r = mg * 8 + rr;
            a[rr] = fmaf(w0, sG[r * C_ + k], a[rr]);
            a[rr] = fmaf(w1, sG[r * C_ + k + 1], a[rr]);
        }
        if (mg == 3) {
            a[8] = fmaf(w0, sG[32 * C_ + k], a[8]);
            a[8] = fmaf(w1, sG[32 * C_ + k + 1], a[8]);
        }
    }
#pragma unroll
    for (int rr = 0; rr < 8; rr++)
        g_M[(b * 33 + mg * 8 + rr) * C_ + c] = a[rr];
    if (mg == 3)
        g_M[(b * 33 + 32) * C_ + c] = a[8];
}

// ---------------- K4: out = A @ M', SIMD-over-k f32x2 ------------------------
// 4096 blocks = 8b x 256 n-slices(64px) x 2 c-halves(96c). 256 thr, 3/SM.
// acc[c-channel] = (k-even partial, k-odd partial); horizontal add at end.
// k padded 33 -> 36 with zero rows. Zero pack-MOVs: ld.shared.v2.u64 pairs.
__global__ void __launch_bounds__(256, 3) k_out(
    const float* __restrict__ gamma, float* __restrict__ out)
{
    extern __shared__ float sm[];
    float* sM2 = sm;           // [18 kk][96 cc][2 e] = 3456 f
    float* sA2 = sm + 3456;    // [9 q][64 px][4 e]   = 2304 f
    __shared__ float sKS[CQ];
    int tid = threadIdx.x;
    int b  = blockIdx.x >> 9;
    int ns = (blockIdx.x >> 1) & 255;
    int ch = blockIdx.x & 1;
    int n0 = ns << 6;
    int c0 = ch * 96;

    // stage M half, k-paired: sM2[kk][cc][e] = M[2kk+e][c0+cc] (0 beyond k=32)
    const float* mb = g_M + b * 33 * C_ + c0;
    for (int i = tid; i < 36 * 96; i += 256) {
        int k = i / 96, cc = i % 96;
        float v = (k < 33) ? mb[k * C_ + cc] : 0.f;
        sM2[(k >> 1) * 192 + cc * 2 + (k & 1)] = v;
    }
    if (tid < CQ) sKS[tid] = g_KS[b * CQ + tid] + EPSF;

    // stage Qn: sA2[q][px][e] = Qn[px][4q+e]
    const float4* qsrc = (const float4*)(g_Qn + ((size_t)b * N_ + n0) * CQ);
    for (int i = tid; i < 512; i += 256) {
        float4 qv = qsrc[i];
        int px = i >> 3, mq = (i & 7) << 2;
        ((float4*)sA2)[(mq >> 2) * 64 + px] = qv;
    }
    __syncthreads();

    float gam = gamma[0];
    if (tid < 64) {
        float dot = 0.f, qv[CQ];
#pragma unroll
        for (int m = 0; m < CQ; m++) {
            qv[m] = sA2[(m >> 2) * 256 + tid * 4 + (m & 3)];
            dot += qv[m] * sKS[m];
        }
        float g = gam / ((float)N_ + dot);
#pragma unroll
        for (int m = 0; m < CQ; m++)
            sA2[(m >> 2) * 256 + tid * 4 + (m & 3)] = qv[m] * g;
        sA2[8 * 256 + tid * 4 + 0] = g;      // A[32] = g (pairs with M row 32=VS)
        sA2[8 * 256 + tid * 4 + 1] = 0.f;
        sA2[8 * 256 + tid * 4 + 2] = 0.f;
        sA2[8 * 256 + tid * 4 + 3] = 0.f;
    }
    __syncthreads();

    int rw = tid & 31, cg = tid >> 5;
    u64 acc[2][12];
#pragma unroll
    for (int i = 0; i < 2; i++)
#pragma unroll
        for (int j = 0; j < 12; j++) acc[i][j] = 0ULL;

#pragma unroll
    for (int q = 0; q < 9; q++) {
        u64 aA0, aB0, aA1, aB1;       // (A[4q],A[4q+1]) , (A[4q+2],A[4q+3])
        lds2(aA0, aB0, sA2 + q * 256 + rw * 4);
        lds2(aA1, aB1, sA2 + q * 256 + (rw + 32) * 4);
        const float* mrow0 = sM2 + (2 * q) * 192;
        const float* mrow1 = mrow0 + 192;
#pragma unroll
        for (int jj = 0; jj < 6; jj++) {
            u64 mlo, mhi;             // (M_k0_c, M_k1_c), (M_k0_c+1, M_k1_c+1)
            lds2(mlo, mhi, mrow0 + (cg + 8 * jj) * 4);
            fma2(acc[0][2 * jj],     aA0, mlo);
            fma2(acc[0][2 * jj + 1], aA0, mhi);
            fma2(acc[1][2 * jj],     aA1, mlo);
            fma2(acc[1][2 * jj + 1], aA1, mhi);
        }
#pragma unroll
        for (int jj = 0; jj < 6; jj++) {
            u64 mlo, mhi;
            lds2(mlo, mhi, mrow1 + (cg + 8 * jj) * 4);
            fma2(acc[0][2 * jj],     aB0, mlo);
            fma2(acc[0][2 * jj + 1], aB0, mhi);
            fma2(acc[1][2 * jj],     aB1, mlo);
            fma2(acc[1][2 * jj + 1], aB1, mhi);
        }
    }

    float* ob = out + (size_t)b * C_ * N_ + (size_t)c0 * N_ + n0 + rw;
#pragma unroll
    for (int i = 0; i < 2; i++)
#pragma unroll
        for (int jj = 0; jj < 6; jj++) {
            int c = 2 * (cg + 8 * jj);
            float lo, hi;
            unpack2(acc[i][2 * jj], lo, hi);
            float v0 = lo + hi;
            unpack2(acc[i][2 * jj + 1], lo, hi);
            float v1 = lo + hi;
            ob[(size_t)c * N_ + 32 * i]       = v0;
            ob[(size_t)(c + 1) * N_ + 32 * i] = v1;
        }
}

// ---------------- launch ------------------------------------------------------
extern "C" void kernel_launch(void* const* d_in, const int* in_sizes, int n_in,
                              void* d_out, int out_size)
{
    const float* x     = (const float*)d_in[0];
    const float* x1    = (const float*)d_in[1];
    const float* Wq    = (const float*)d_in[2];
    const float* bq    = (const float*)d_in[3];
    const float* Wk    = (const float*)d_in[4];
    const float* bk    = (const float*)d_in[5];
    const float* Wv    = (const float*)d_in[6];
    const float* bv    = (const float*)d_in[7];
    const float* gamma = (const float*)d_in[8];
    float* out = (float*)d_out;

    static int inited = 0;
    if (!inited) {
        cudaFuncSetAttribute(k_qk,    cudaFuncAttributeMaxDynamicSharedMemorySize, 69632);
        cudaFuncSetAttribute(k_gmat,  cudaFuncAttributeMaxDynamicSharedMemorySize, 57856);
        cudaFuncSetAttribute(k_small, cudaFuncAttributeMaxDynamicSharedMemorySize, 50080);
        cudaFuncSetAttribute(k_out,   cudaFuncAttributeMaxDynamicSharedMemorySize, 23040);
        inited = 1;
    }

    k_qk   <<<1024, 256, 69632>>>(x1, Wq, bq, Wk, bk);
    k_gmat <<<512, 256, 57856>>>(x);
    k_small<<<48, 128, 50080>>>(Wv, bv);
    k_out  <<<4096, 256, 23040>>>(gamma, out);
}

// round 7
// speedup vs baseline: 1.7479x; 1.7479x over previous
#include <cuda_runtime.h>

#define B_   8
#define C_   192
#define CQ   32
#define N_   16384
#define NPIX (B_ * N_)
#define EPSF 1e-6f

typedef unsigned long long u64;

// ---------------- scratch ---------------------------------------------------
__device__ float g_Qn[(size_t)NPIX * CQ];   // [px][32] normalized Q
__device__ float g_Kn[(size_t)NPIX * CQ];   // [px][32] normalized K
__device__ float g_G[B_ * 33 * C_];         // rows 0..31: G[m][k]; row 32: xsum[k]
__device__ float g_KS[B_ * CQ];             // sum_n Kn
__device__ float g_M[B_ * 33 * C_];         // rows 0..31: matrix[m][c]; row 32: value_sum[c]

// ---------------- helpers ----------------------------------------------------
__device__ __forceinline__ u64 pack2(float lo, float hi) {
    u64 r;
    asm("mov.b64 %0, {%1, %2};" : "=l"(r)
        : "r"(__float_as_uint(lo)), "r"(__float_as_uint(hi)));
    return r;
}
__device__ __forceinline__ void unpack2(u64 v, float& lo, float& hi) {
    unsigned a, b;
    asm("mov.b64 {%0, %1}, %2;" : "=r"(a), "=r"(b) : "l"(v));
    lo = __uint_as_float(a); hi = __uint_as_float(b);
}
__device__ __forceinline__ void fma2(u64& d, u64 a, u64 b) {
    asm("fma.rn.f32x2 %0, %1, %2, %0;" : "+l"(d) : "l"(a), "l"(b));
}
__device__ __forceinline__ void red2(float* p, float lo, float hi) {
    asm volatile("red.global.add.v2.f32 [%0], {%1, %2};"
                 :: "l"(p), "f"(lo), "f"(hi) : "memory");
}
__device__ __forceinline__ void cpa16(const float* dst, const void* src) {
    asm volatile("cp.async.cg.shared.global [%0], [%1], 16;"
                 :: "l"(__cvta_generic_to_shared(dst)), "l"(src));
}
__device__ __forceinline__ void cpa_commit() { asm volatile("cp.async.commit_group;"); }
__device__ __forceinline__ void cpa_wait0()  { asm volatile("cp.async.wait_group 0;" ::: "memory"); }
__device__ __forceinline__ void cpa_wait1()  { asm volatile("cp.async.wait_group 1;" ::: "memory"); }

// ---------------- K1: Q/K projection + L2 norm (also zeroes G/KS) ------------
// 1024 blocks (8b x 128 slices of 128 px), 256 threads, 3 blocks/SM.
// Thread: 2 px x 8 out-pairs. x staged in 8-k chunks, double-buffered cp.async
// (one 16B LDGSTS per thread per chunk). Weights: conflict-free LDS.128.
__global__ void __launch_bounds__(256, 3) k_qk(
    const float* __restrict__ x1,
    const float* __restrict__ Wq, const float* __restrict__ bq,
    const float* __restrict__ Wk, const float* __restrict__ bk)
{
    extern __shared__ float sm[];
    float*  sW = sm;                       // 192 rows * 40 float2 = 61440B = 15360 f
    float*  sX = sm + 15360;               // 2 x [8][128] = 8192B  (total 69632B)

    int tid = threadIdx.x;
    int col = tid & 3, row = tid >> 2;
    int b   = blockIdx.x >> 7;
    int n0  = (blockIdx.x & 127) << 7;
    const float* xb = x1 + (size_t)b * C_ * N_ + n0;

    // zero accumulators for k_gmat
    {
        int z = blockIdx.x * 256 + tid;
        if (z < B_ * 33 * C_) g_G[z] = 0.0f;
        int zk = z - B_ * 33 * C_;
        if (zk >= 0 && zk < B_ * CQ) g_KS[zk] = 0.0f;
    }

    // stage weights: pair o (0..31) of [Q|K]; float2 at k*40+col*10+q*2+e
    for (int i = tid; i < 32 * C_; i += 256) {
        int o = i / C_, k = i % C_;
        int c0 = o >> 3, jj = o & 7, q = jj >> 1, e = jj & 1;
        float lo, hi;
        if (o < 16) { lo = Wq[(2 * o) * C_ + k];           hi = Wq[(2 * o + 1) * C_ + k]; }
        else { int oo = o - 16; lo = Wk[(2 * oo) * C_ + k]; hi = Wk[(2 * oo + 1) * C_ + k]; }
        ((float2*)sW)[k * 40 + c0 * 10 + q * 2 + e] = make_float2(lo, hi);
    }

    u64 acc[2][8];
#pragma unroll
    for (int jj = 0; jj < 8; jj++) {
        int o = col * 8 + jj;
        float lo, hi;
        if (o < 16) { lo = bq[2 * o]; hi = bq[2 * o + 1]; }
        else        { lo = bk[2 * (o - 16)]; hi = bk[2 * (o - 16) + 1]; }
        acc[0][jj] = pack2(lo, hi);
        acc[1][jj] = acc[0][jj];
    }

    // cp.async staging coords: thread covers one 16B segment per chunk
    int tt  = tid >> 5;            // k-row within chunk (0..7)
    int px4 = (tid & 31) * 4;      // pixel base (0..124)

    // prefetch chunk 0
    cpa16(sX + tt * 128 + px4, xb + (size_t)tt * N_ + px4);
    cpa_commit();
    __syncthreads();               // also covers weight staging

    const float4* sW4 = (const float4*)sW;
    for (int s = 0; s < 24; s++) {
        if (s < 23) {
            float* nb = sX + ((s + 1) & 1) * 1024;
            cpa16(nb + tt * 128 + px4, xb + (size_t)((s + 1) * 8 + tt) * N_ + px4);
            cpa_commit();
            cpa_wait1();           // chunk s resident (chunk s+1 in flight)
        } else {
            cpa_wait0();
        }
        __syncthreads();

        const float* cb = sX + (s & 1) * 1024;
        int ks = s * 8;
#pragma unroll
        for (int t = 0; t < 8; t++) {
            float xv0 = cb[t * 128 + row];
            float xv1 = cb[t * 128 + row + 64];
            u64 x20 = pack2(xv0, xv0);
            u64 x21 = pack2(xv1, xv1);
            int base = (ks + t) * 20 + col * 5;
#pragma unroll
            for (int q = 0; q < 4; q++) {
                float4 w4 = sW4[base + q];
                u64 wa = pack2(w4.x, w4.y);
                u64 wb = pack2(w4.z, w4.w);
                fma2(acc[0][2 * q],     wa, x20);
                fma2(acc[0][2 * q + 1], wb, x20);
                fma2(acc[1][2 * q],     wa, x21);
                fma2(acc[1][2 * q + 1], wb, x21);
            }
        }
        __syncthreads();           // protect buffer s&1 from chunk s+2 issue
    }

    // epilogue: unpack, L2 normalize (halves joined via shfl_xor 1)
    float v[2][16], s2[2];
#pragma unroll
    for (int i = 0; i < 2; i++) {
        s2[i] = 0.f;
#pragma unroll
        for (int jj = 0; jj < 8; jj++) {
            unpack2(acc[i][jj], v[i][2 * jj], v[i][2 * jj + 1]);
            s2[i] += v[i][2 * jj] * v[i][2 * jj] + v[i][2 * jj + 1] * v[i][2 * jj + 1];
        }
    }
#pragma unroll
    for (int i = 0; i < 2; i++) {
        s2[i] += __shfl_xor_sync(0xffffffffu, s2[i], 1);
        float r = rsqrtf(s2[i]);
#pragma unroll
        for (int t = 0; t < 16; t++) v[i][t] *= r;
    }

    float* dst = (col < 2) ? g_Qn : g_Kn;
    int half = (col & 1) << 4;
    int pxb = b * N_ + n0 + row;
#pragma unroll
    for (int i = 0; i < 2; i++) {
        float4* o4 = (float4*)(dst + (size_t)(pxb + 64 * i) * CQ + half);
#pragma unroll
        for (int jj = 0; jj < 4; jj++)
            o4[jj] = make_float4(v[i][4 * jj], v[i][4 * jj + 1],
                                 v[i][4 * jj + 2], v[i][4 * jj + 3]);
    }
}

// ---------------- K2: G = Kn @ x^T  (+ xsum, + KSum) --------------------------
// 512 blocks = 8 b x 64 n-slices of 256, 256 threads, 2 blocks/SM.
// Thread tile: 4 m (mg=tid&7) x 3 c-pairs (c2 = cg + 32*j, cg=tid>>3).
__global__ void __launch_bounds__(256, 2) k_gmat(const float* __restrict__ x)
{
    __shared__ __align__(16) float sXT[32][194];
    __shared__ __align__(16) float sKn[32][32];
    int tid = threadIdx.x;
    int w = tid >> 5, p = tid & 31;
    int mg = tid & 7, cg = tid >> 3;
    int b  = blockIdx.x >> 6;
    int n0 = (blockIdx.x & 63) << 8;

    const float* xb = x + (size_t)b * C_ * N_ + n0;
    const float4* knb = (const float4*)(g_Kn + ((size_t)b * N_ + n0) * CQ);

    u64 acc[4][3];
#pragma unroll
    for (int mi = 0; mi < 4; mi++)
#pragma unroll
        for (int j = 0; j < 3; j++) acc[mi][j] = 0ULL;
    float xs[24];
#pragma unroll
    for (int j = 0; j < 24; j++) xs[j] = 0.f;
    float ksacc = 0.f;

    for (int s = 0; s < 8; s++) {
        __syncthreads();
#pragma unroll
        for (int j = 0; j < 24; j++) {
            int c = w * 24 + j;
            float vx = xb[(size_t)c * N_ + s * 32 + p];
            sXT[p][c] = vx;
            xs[j] += vx;
        }
        ((float4*)&sKn[0][0])[tid] = knb[s * 256 + tid];
        __syncthreads();

        if (tid < 32) {            // KSum partial: column tid of the Kn tile
#pragma unroll
            for (int pp = 0; pp < 32; pp++) ksacc += sKn[pp][tid];
        }

#pragma unroll 4
        for (int pp = 0; pp < 32; pp++) {
            float4 kv = *(const float4*)&sKn[pp][mg * 4];
            u64 k2a = pack2(kv.x, kv.x), k2b = pack2(kv.y, kv.y);
            u64 k2c = pack2(kv.z, kv.z), k2d = pack2(kv.w, kv.w);
#pragma unroll
            for (int j = 0; j < 3; j++) {
                u64 xv2 = *(const u64*)&sXT[pp][2 * (cg + 32 * j)];
                fma2(acc[0][j], k2a, xv2);
                fma2(acc[1][j], k2b, xv2);
                fma2(acc[2][j], k2c, xv2);
                fma2(acc[3][j], k2d, xv2);
            }
        }
    }

    float* gb = g_G + b * 33 * C_;
#pragma unroll
    for (int mi = 0; mi < 4; mi++)
#pragma unroll
        for (int j = 0; j < 3; j++) {
            float lo, hi; unpack2(acc[mi][j], lo, hi);
            red2(gb + (mg * 4 + mi) * C_ + 2 * (cg + 32 * j), lo, hi);
        }
#pragma unroll
    for (int j = 0; j < 24; j++) {
        float vv = xs[j];
        vv += __shfl_xor_sync(0xffffffffu, vv, 16);
        vv += __shfl_xor_sync(0xffffffffu, vv, 8);
        vv += __shfl_xor_sync(0xffffffffu, vv, 4);
        vv += __shfl_xor_sync(0xffffffffu, vv, 2);
        vv += __shfl_xor_sync(0xffffffffu, vv, 1);
        if (p == 0) atomicAdd(gb + 32 * C_ + w * 24 + j, vv);
    }
    if (tid < 32) atomicAdd(&g_KS[b * CQ + tid], ksacc);
}

// ---------------- K3: M' = Ghat @ Wv^T + outer(coef, bv) ---------------------
__global__ void __launch_bounds__(128) k_small(
    const float* __restrict__ Wv, const float* __restrict__ bv)
{
    extern __shared__ float sm[];
    float* sG  = sm;                  // [33][192]
    float* sWv = sm + 33 * C_;        // [32][193]
    int tid = threadIdx.x;
    int b  = blockIdx.x / 6;
    int ct = blockIdx.x % 6;
    int cl = tid & 31, mg = tid >> 5;
    int c  = ct * 32 + cl;

    for (int i = tid; i < 33 * C_; i += 128) sG[i] = g_G[b * 33 * C_ + i];
    for (int i = tid; i < 32 * C_; i += 128) {
        int cc = i / C_, k = i % C_;
        sWv[cc * 193 + k] = Wv[(size_t)(ct * 32 + cc) * C_ + k];
    }
    __syncthreads();

    float bvc = bv[c];
    float a[9];
#pragma unroll
    for (int rr = 0; rr < 8; rr++) a[rr] = g_KS[b * CQ + mg * 8 + rr] * bvc;
    a[8] = (float)N_ * bvc;

    const float* wp = sWv + cl * 193;
    for (int k = 0; k < C_; k += 2) {
        float w0 = wp[k], w1 = wp[k + 1];
#pragma unroll
        for (int rr = 0; rr < 8; rr++) {
            int r = mg * 8 + rr;
            a[rr] = fmaf(w0, sG[r * C_ + k], a[rr]);
            a[rr] = fmaf(w1, sG[r * C_ + k + 1], a[rr]);
        }
        if (mg == 3) {
            a[8] = fmaf(w0, sG[32 * C_ + k], a[8]);
            a[8] = fmaf(w1, sG[32 * C_ + k + 1], a[8]);
        }
    }
#pragma unroll
    for (int rr = 0; rr < 8; rr++)
        g_M[(b * 33 + mg * 8 + rr) * C_ + c] = a[rr];
    if (mg == 3)
        g_M[(b * 33 + 32) * C_ + c] = a[8];
}

// ---------------- K4: out[n,c] = A[n,0..32] @ M'[0..32,c] --------------------
// 2048 blocks (8b x 256 slices of 64 px), 256 threads, 3 blocks/SM.
// Thread: 2 px (rw, rw+32) x 12 c-pairs (float4 m = cg + 8*jj, broadcast LDS.128).
__global__ void __launch_bounds__(256, 3) k_out(
    const float* __restrict__ gamma, float* __restrict__ out)
{
    extern __shared__ float sm[];
    float* sM  = sm;                  // [33][192]  25344B
    float* sAf = sm + 33 * C_;        // [33][68]    8976B
    __shared__ float sKS[CQ];
    int tid = threadIdx.x;
    int b  = blockIdx.x >> 8;
    int n0 = (blockIdx.x & 255) << 6;

    const float4* msrc = (const float4*)(g_M + b * 33 * C_);
    for (int i = tid; i < 33 * C_ / 4; i += 256) ((float4*)sM)[i] = msrc[i];
    if (tid < CQ) sKS[tid] = g_KS[b * CQ + tid] + EPSF;

    const float4* qsrc = (const float4*)(g_Qn + ((size_t)b * N_ + n0) * CQ);
    for (int i = tid; i < 512; i += 256) {
        float4 qv = qsrc[i];
        int px = i >> 3, mb = (i & 7) * 4;
        sAf[(mb + 0) * 68 + px] = qv.x;
        sAf[(mb + 1) * 68 + px] = qv.y;
        sAf[(mb + 2) * 68 + px] = qv.z;
        sAf[(mb + 3) * 68 + px] = qv.w;
    }
    __syncthreads();

    float gam = gamma[0];
    if (tid < 64) {
        float dot = 0.f, qv[CQ];
#pragma unroll
        for (int m = 0; m < CQ; m++) { qv[m] = sAf[m * 68 + tid]; dot += qv[m] * sKS[m]; }
        float g = gam / ((float)N_ + dot);
#pragma unroll
        for (int m = 0; m < CQ; m++) sAf[m * 68 + tid] = qv[m] * g;
        sAf[32 * 68 + tid] = g;
    }
    __syncthreads();

    int rw = tid & 31, cg = tid >> 5;
    u64 acc[2][12];
#pragma unroll
    for (int i = 0; i < 2; i++)
#pragma unroll
        for (int j = 0; j < 12; j++) acc[i][j] = 0ULL;

#pragma unroll 3
    for (int k = 0; k < 33; k++) {
        float a0 = sAf[k * 68 + rw];
        float a1 = sAf[k * 68 + rw + 32];
        u64 a20 = pack2(a0, a0);
        u64 a21 = pack2(a1, a1);
        const float4* m4 = (const float4*)(sM + k * C_);
#pragma unroll
        for (int jj = 0; jj < 6; jj++) {
            float4 mv = m4[cg + 8 * jj];           // broadcast per warp
            u64 mlo = pack2(mv.x, mv.y), mhi = pack2(mv.z, mv.w);
            fma2(acc[0][2 * jj],     a20, mlo);
            fma2(acc[0][2 * jj + 1], a20, mhi);
            fma2(acc[1][2 * jj],     a21, mlo);
            fma2(acc[1][2 * jj + 1], a21, mhi);
        }
    }

    float* ob = out + (size_t)b * C_ * N_ + n0 + rw;
#pragma unroll
    for (int i = 0; i < 2; i++)
#pragma unroll
        for (int jj = 0; jj < 6; jj++) {
            int c = 4 * (cg + 8 * jj);
            float lo, hi;
            unpack2(acc[i][2 * jj], lo, hi);
            ob[(size_t)c * N_ + 32 * i]       = lo;
            ob[(size_t)(c + 1) * N_ + 32 * i] = hi;
            unpack2(acc[i][2 * jj + 1], lo, hi);
            ob[(size_t)(c + 2) * N_ + 32 * i] = lo;
            ob[(size_t)(c + 3) * N_ + 32 * i] = hi;
        }
}

// ---------------- launch ------------------------------------------------------
extern "C" void kernel_launch(void* const* d_in, const int* in_sizes, int n_in,
                              void* d_out, int out_size)
{
    const float* x     = (const float*)d_in[0];
    const float* x1    = (const float*)d_in[1];
    const float* Wq    = (const float*)d_in[2];
    const float* bq    = (const float*)d_in[3];
    const float* Wk    = (const float*)d_in[4];
    const float* bk    = (const float*)d_in[5];
    const float* Wv    = (const float*)d_in[6];
    const float* bv    = (const float*)d_in[7];
    const float* gamma = (const float*)d_in[8];
    float* out = (float*)d_out;

    static int inited = 0;
    if (!inited) {
        cudaFuncSetAttribute(k_qk,    cudaFuncAttributeMaxDynamicSharedMemorySize, 69632);
        cudaFuncSetAttribute(k_small, cudaFuncAttributeMaxDynamicSharedMemorySize, 50080);
        cudaFuncSetAttribute(k_out,   cudaFuncAttributeMaxDynamicSharedMemorySize, 34320);
        inited = 1;
    }

    k_qk   <<<1024, 256, 69632>>>(x1, Wq, bq, Wk, bk);
    k_gmat <<<512, 256>>>(x);
    k_small<<<48, 128, 50080>>>(Wv, bv);
    k_out  <<<2048, 256, 34320>>>(gamma, out);
}

// round 8
// speedup vs baseline: 1.8862x; 1.0791x over previous
#include <cuda_runtime.h>

#define B_   8
#define C_   192
#define CQ   32
#define N_   16384
#define NPIX (B_ * N_)
#define EPSF 1e-6f

typedef unsigned long long u64;

// ---------------- scratch ---------------------------------------------------
__device__ float g_Qn[(size_t)NPIX * CQ];   // [px][32] normalized Q
__device__ float g_Kn[(size_t)NPIX * CQ];   // [px][32] normalized K
__device__ float g_G[B_ * 33 * C_];         // rows 0..31: G[m][k]; row 32: xsum[k]
__device__ float g_KS[B_ * CQ];             // sum_n Kn
__device__ float g_M[B_ * 33 * C_];         // rows 0..31: matrix[m][c]; row 32: value_sum[c]

// ---------------- helpers ----------------------------------------------------
__device__ __forceinline__ u64 pack2(float lo, float hi) {
    u64 r;
    asm("mov.b64 %0, {%1, %2};" : "=l"(r)
        : "r"(__float_as_uint(lo)), "r"(__float_as_uint(hi)));
    return r;
}
__device__ __forceinline__ void unpack2(u64 v, float& lo, float& hi) {
    unsigned a, b;
    asm("mov.b64 {%0, %1}, %2;" : "=r"(a), "=r"(b) : "l"(v));
    lo = __uint_as_float(a); hi = __uint_as_float(b);
}
__device__ __forceinline__ void fma2(u64& d, u64 a, u64 b) {
    asm("fma.rn.f32x2 %0, %1, %2, %0;" : "+l"(d) : "l"(a), "l"(b));
}
__device__ __forceinline__ void red2(float* p, float lo, float hi) {
    asm volatile("red.global.add.v2.f32 [%0], {%1, %2};"
                 :: "l"(p), "f"(lo), "f"(hi) : "memory");
}
__device__ __forceinline__ void cpa16(const float* dst, const void* src) {
    asm volatile("cp.async.cg.shared.global [%0], [%1], 16;"
                 :: "l"(__cvta_generic_to_shared(dst)), "l"(src));
}
__device__ __forceinline__ void cpa_commit() { asm volatile("cp.async.commit_group;"); }
__device__ __forceinline__ void cpa_wait0()  { asm volatile("cp.async.wait_group 0;" ::: "memory"); }
__device__ __forceinline__ void cpa_wait1()  { asm volatile("cp.async.wait_group 1;" ::: "memory"); }

// ---------------- K1: Q/K projection + L2 norm (also zeroes G/KS) ------------
// 1024 blocks (8b x 128 slices of 128 px), 256 threads, 3 blocks/SM.
// Thread: 2 px x 8 out-pairs. x staged in 8-k chunks via a 3-buffer cp.async
// ring -> ONE barrier per chunk. Weights: conflict-free broadcast LDS.128.
__global__ void __launch_bounds__(256, 3) k_qk(
    const float* __restrict__ x1,
    const float* __restrict__ Wq, const float* __restrict__ bq,
    const float* __restrict__ Wk, const float* __restrict__ bk)
{
    extern __shared__ float sm[];
    float*  sW = sm;                       // 192 rows * 40 float2 = 61440B = 15360 f
    float*  sX = sm + 15360;               // 3 x [8][128] = 12288B (total 73728B)

    int tid = threadIdx.x;
    int col = tid & 3, row = tid >> 2;
    int b   = blockIdx.x >> 7;
    int n0  = (blockIdx.x & 127) << 7;
    const float* xb = x1 + (size_t)b * C_ * N_ + n0;

    // zero accumulators for k_gmat
    {
        int z = blockIdx.x * 256 + tid;
        if (z < B_ * 33 * C_) g_G[z] = 0.0f;
        int zk = z - B_ * 33 * C_;
        if (zk >= 0 && zk < B_ * CQ) g_KS[zk] = 0.0f;
    }

    // stage weights: pair o (0..31) of [Q|K]; float2 at k*40+col*10+q*2+e
    for (int i = tid; i < 32 * C_; i += 256) {
        int o = i / C_, k = i % C_;
        int c0 = o >> 3, jj = o & 7, q = jj >> 1, e = jj & 1;
        float lo, hi;
        if (o < 16) { lo = Wq[(2 * o) * C_ + k];           hi = Wq[(2 * o + 1) * C_ + k]; }
        else { int oo = o - 16; lo = Wk[(2 * oo) * C_ + k]; hi = Wk[(2 * oo + 1) * C_ + k]; }
        ((float2*)sW)[k * 40 + c0 * 10 + q * 2 + e] = make_float2(lo, hi);
    }

    u64 acc[2][8];
#pragma unroll
    for (int jj = 0; jj < 8; jj++) {
        int o = col * 8 + jj;
        float lo, hi;
        if (o < 16) { lo = bq[2 * o]; hi = bq[2 * o + 1]; }
        else        { lo = bk[2 * (o - 16)]; hi = bk[2 * (o - 16) + 1]; }
        acc[0][jj] = pack2(lo, hi);
        acc[1][jj] = acc[0][jj];
    }

    // cp.async staging coords: thread covers one 16B segment per chunk
    int tt  = tid >> 5;            // k-row within chunk (0..7)
    int px4 = (tid & 31) * 4;      // pixel base (0..124)

    // prefetch chunk 0 into buffer 0
    cpa16(sX + tt * 128 + px4, xb + (size_t)tt * N_ + px4);
    cpa_commit();

    const float4* sW4 = (const float4*)sW;
    int bufn = 1024;               // floats per buffer
    for (int s = 0; s < 24; s++) {
        if (s < 23) {
            float* nb = sX + ((s + 1) % 3) * bufn;
            cpa16(nb + tt * 128 + px4, xb + (size_t)((s + 1) * 8 + tt) * N_ + px4);
            cpa_commit();
            cpa_wait1();           // chunk s resident (chunk s+1 in flight)
        } else {
            cpa_wait0();
        }
        __syncthreads();           // single barrier per chunk (3-buffer ring)

        const float* cb = sX + (s % 3) * bufn;
        int ks = s * 8;
#pragma unroll
        for (int t = 0; t < 8; t++) {
            float xv0 = cb[t * 128 + row];
            float xv1 = cb[t * 128 + row + 64];
            u64 x20 = pack2(xv0, xv0);
            u64 x21 = pack2(xv1, xv1);
            int base = (ks + t) * 20 + col * 5;
#pragma unroll
            for (int q = 0; q < 4; q++) {
                float4 w4 = sW4[base + q];
                u64 wa = pack2(w4.x, w4.y);
                u64 wb = pack2(w4.z, w4.w);
                fma2(acc[0][2 * q],     wa, x20);
                fma2(acc[0][2 * q + 1], wb, x20);
                fma2(acc[1][2 * q],     wa, x21);
                fma2(acc[1][2 * q + 1], wb, x21);
            }
        }
    }

    // epilogue: unpack, L2 normalize (halves joined via shfl_xor 1)
    float v[2][16], s2[2];
#pragma unroll
    for (int i = 0; i < 2; i++) {
        s2[i] = 0.f;
#pragma unroll
        for (int jj = 0; jj < 8; jj++) {
            unpack2(acc[i][jj], v[i][2 * jj], v[i][2 * jj + 1]);
            s2[i] += v[i][2 * jj] * v[i][2 * jj] + v[i][2 * jj + 1] * v[i][2 * jj + 1];
        }
    }
#pragma unroll
    for (int i = 0; i < 2; i++) {
        s2[i] += __shfl_xor_sync(0xffffffffu, s2[i], 1);
        float r = rsqrtf(s2[i]);
#pragma unroll
        for (int t = 0; t < 16; t++) v[i][t] *= r;
    }

    float* dst = (col < 2) ? g_Qn : g_Kn;
    int half = (col & 1) << 4;
    int pxb = b * N_ + n0 + row;
#pragma unroll
    for (int i = 0; i < 2; i++) {
        float4* o4 = (float4*)(dst + (size_t)(pxb + 64 * i) * CQ + half);
#pragma unroll
        for (int jj = 0; jj < 4; jj++)
            o4[jj] = make_float4(v[i][4 * jj], v[i][4 * jj + 1],
                                 v[i][4 * jj + 2], v[i][4 * jj + 3]);
    }
}

// ---------------- K2: G = Kn @ x^T  (+ xsum, + KSum), register prefetch ------
// 512 blocks = 8 b x 64 n-slices of 256, 256 threads, 2 blocks/SM.
// Tile s+1 loaded into registers while tile s computes; STS after compute.
__global__ void __launch_bounds__(256, 2) k_gmat(const float* __restrict__ x)
{
    __shared__ __align__(16) float sXT[32][194];
    __shared__ __align__(16) float sKn[32][32];
    int tid = threadIdx.x;
    int w = tid >> 5, p = tid & 31;
    int mg = tid & 7, cg = tid >> 3;
    int b  = blockIdx.x >> 6;
    int n0 = (blockIdx.x & 63) << 8;

    const float* xb = x + (size_t)b * C_ * N_ + n0;
    const float4* knb = (const float4*)(g_Kn + ((size_t)b * N_ + n0) * CQ);

    u64 acc[4][3];
#pragma unroll
    for (int mi = 0; mi < 4; mi++)
#pragma unroll
        for (int j = 0; j < 3; j++) acc[mi][j] = 0ULL;
    float xs[24];
#pragma unroll
    for (int j = 0; j < 24; j++) xs[j] = 0.f;
    float ksacc = 0.f;

    // stage tile 0
    {
        float xr[24];
#pragma unroll
        for (int j = 0; j < 24; j++)
            xr[j] = xb[(size_t)(w * 24 + j) * N_ + p];
        float4 knr = knb[tid];
#pragma unroll
        for (int j = 0; j < 24; j++) { sXT[p][w * 24 + j] = xr[j]; xs[j] += xr[j]; }
        ((float4*)&sKn[0][0])[tid] = knr;
    }
    __syncthreads();

    for (int s = 0; s < 8; s++) {
        float xr[24]; float4 knr;
        if (s < 7) {                       // prefetch tile s+1 into registers
#pragma unroll
            for (int j = 0; j < 24; j++)
                xr[j] = xb[(size_t)(w * 24 + j) * N_ + (s + 1) * 32 + p];
            knr = knb[(s + 1) * 256 + tid];
        }

        if (tid < 32) {                    // KSum partial: column tid
#pragma unroll
            for (int pp = 0; pp < 32; pp++) ksacc += sKn[pp][tid];
        }

#pragma unroll 4
        for (int pp = 0; pp < 32; pp++) {
            float4 kv = *(const float4*)&sKn[pp][mg * 4];
            u64 k2a = pack2(kv.x, kv.x), k2b = pack2(kv.y, kv.y);
            u64 k2c = pack2(kv.z, kv.z), k2d = pack2(kv.w, kv.w);
#pragma unroll
            for (int j = 0; j < 3; j++) {
                u64 xv2 = *(const u64*)&sXT[pp][2 * (cg + 32 * j)];
                fma2(acc[0][j], k2a, xv2);
                fma2(acc[1][j], k2b, xv2);
                fma2(acc[2][j], k2c, xv2);
                fma2(acc[3][j], k2d, xv2);
            }
        }
        __syncthreads();                   // everyone done reading tile s
        if (s < 7) {
#pragma unroll
            for (int j = 0; j < 24; j++) { sXT[p][w * 24 + j] = xr[j]; xs[j] += xr[j]; }
            ((float4*)&sKn[0][0])[tid] = knr;
            __syncthreads();               // tile s+1 visible
        }
    }

    float* gb = g_G + b * 33 * C_;
#pragma unroll
    for (int mi = 0; mi < 4; mi++)
#pragma unroll
        for (int j = 0; j < 3; j++) {
            float lo, hi; unpack2(acc[mi][j], lo, hi);
            red2(gb + (mg * 4 + mi) * C_ + 2 * (cg + 32 * j), lo, hi);
        }
#pragma unroll
    for (int j = 0; j < 24; j++) {
        float vv = xs[j];
        vv += __shfl_xor_sync(0xffffffffu, vv, 16);
        vv += __shfl_xor_sync(0xffffffffu, vv, 8);
        vv += __shfl_xor_sync(0xffffffffu, vv, 4);
        vv += __shfl_xor_sync(0xffffffffu, vv, 2);
        vv += __shfl_xor_sync(0xffffffffu, vv, 1);
        if (p == 0) atomicAdd(gb + 32 * C_ + w * 24 + j, vv);
    }
    if (tid < 32) atomicAdd(&g_KS[b * CQ + tid], ksacc);
}

// ---------------- K3: M' = Ghat @ Wv^T + outer(coef, bv) ---------------------
__global__ void __launch_bounds__(128) k_small(
    const float* __restrict__ Wv, const float* __restrict__ bv)
{
    extern __shared__ float sm[];
    float* sG  = sm;                  // [33][192]
    float* sWv = sm + 33 * C_;        // [32][193]
    int tid = threadIdx.x;
    int b  = blockIdx.x / 6;
    int ct = blockIdx.x % 6;
    int cl = tid & 31, mg = tid >> 5;
    int c  = ct * 32 + cl;

    for (int i = tid; i < 33 * C_; i += 128) sG[i] = g_G[b * 33 * C_ + i];
    for (int i = tid; i < 32 * C_; i += 128) {
        int cc = i / C_, k = i % C_;
        sWv[cc * 193 + k] = Wv[(size_t)(ct * 32 + cc) * C_ + k];
    }
    __syncthreads();

    float bvc = bv[c];
    float a[9];
#pragma unroll
    for (int rr = 0; rr < 8; rr++) a[rr] = g_KS[b * CQ + mg * 8 + rr] * bvc;
    a[8] = (float)N_ * bvc;

    const float* wp = sWv + cl * 193;
    for (int k = 0; k < C_; k += 2) {
        float w0 = wp[k], w1 = wp[k + 1];
#pragma unroll
        for (int rr = 0; rr < 8; rr++) {
            int r = mg * 8 + rr;
            a[rr] = fmaf(w0, sG[r * C_ + k], a[rr]);
            a[rr] = fmaf(w1, sG[r * C_ + k + 1], a[rr]);
        }
        if (mg == 3) {
            a[8] = fmaf(w0, sG[32 * C_ + k], a[8]);
            a[8] = fmaf(w1, sG[32 * C_ + k + 1], a[8]);
        }
    }
#pragma unroll
    for (int rr = 0; rr < 8; rr++)
        g_M[(b * 33 + mg * 8 + rr) * C_ + c] = a[rr];
    if (mg == 3)
        g_M[(b * 33 + 32) * C_ + c] = a[8];
}

// ---------------- K4: out[n,c] = A[n,0..32] @ M'[0..32,c], c-half split ------
// 4096 blocks (8b x 256 n-slices(64px) x 2 c-halves(96c)), 256 thr, 4 blocks/SM.
// Thread: 2 px (rw, rw+32) x 6 c-pairs (float4 m = cg + 8*jj, broadcast LDS.128).
__global__ void __launch_bounds__(256, 4) k_out(
    const float* __restrict__ gamma, float* __restrict__ out)
{
    extern __shared__ float sm[];
    float* sM  = sm;                  // [33][96]   12672B
    float* sAf = sm + 33 * 96;        // [33][68]    8976B  (total 21648B)
    __shared__ float sKS[CQ];
    int tid = threadIdx.x;
    int b  = blockIdx.x >> 9;
    int ns = (blockIdx.x >> 1) & 255;
    int ch = blockIdx.x & 1;
    int n0 = ns << 6;

    // stage M half (96 channels)
    const float* mb = g_M + b * 33 * C_ + ch * 96;
    for (int i = tid; i < 33 * 24; i += 256) {
        int k = i / 24, q = i % 24;
        ((float4*)(sM + k * 96))[q] = ((const float4*)(mb + k * C_))[q];
    }
    if (tid < CQ) sKS[tid] = g_KS[b * CQ + tid] + EPSF;

    const float4* qsrc = (const float4*)(g_Qn + ((size_t)b * N_ + n0) * CQ);
    for (int i = tid; i < 512; i += 256) {
        float4 qv = qsrc[i];
        int px = i >> 3, mq = (i & 7) * 4;
        sAf[(mq + 0) * 68 + px] = qv.x;
        sAf[(mq + 1) * 68 + px] = qv.y;
        sAf[(mq + 2) * 68 + px] = qv.z;
        sAf[(mq + 3) * 68 + px] = qv.w;
    }
    __syncthreads();

    float gam = gamma[0];
    if (tid < 64) {
        float dot = 0.f, qv[CQ];
#pragma unroll
        for (int m = 0; m < CQ; m++) { qv[m] = sAf[m * 68 + tid]; dot += qv[m] * sKS[m]; }
        float g = gam / ((float)N_ + dot);
#pragma unroll
        for (int m = 0; m < CQ; m++) sAf[m * 68 + tid] = qv[m] * g;
        sAf[32 * 68 + tid] = g;
    }
    __syncthreads();

    int rw = tid & 31, cg = tid >> 5;
    u64 acc[2][6];
#pragma unroll
    for (int i = 0; i < 2; i++)
#pragma unroll
        for (int j = 0; j < 6; j++) acc[i][j] = 0ULL;

#pragma unroll 3
    for (int k = 0; k < 33; k++) {
        float a0 = sAf[k * 68 + rw];
        float a1 = sAf[k * 68 + rw + 32];
        u64 a20 = pack2(a0, a0);
        u64 a21 = pack2(a1, a1);
        const float4* m4 = (const float4*)(sM + k * 96);
#pragma unroll
        for (int jj = 0; jj < 3; jj++) {
            float4 mv = m4[cg + 8 * jj];           // broadcast per warp
            u64 mlo = pack2(mv.x, mv.y), mhi = pack2(mv.z, mv.w);
            fma2(acc[0][2 * jj],     a20, mlo);
            fma2(acc[0][2 * jj + 1], a20, mhi);
            fma2(acc[1][2 * jj],     a21, mlo);
            fma2(acc[1][2 * jj + 1], a21, mhi);
        }
    }

    float* ob = out + (size_t)b * C_ * N_ + (size_t)(ch * 96) * N_ + n0 + rw;
#pragma unroll
    for (int i = 0; i < 2; i++)
#pragma unroll
        for (int jj = 0; jj < 3; jj++) {
            int c = 4 * (cg + 8 * jj);
            float lo, hi;
            unpack2(acc[i][2 * jj], lo, hi);
            ob[(size_t)c * N_ + 32 * i]       = lo;
            ob[(size_t)(c + 1) * N_ + 32 * i] = hi;
            unpack2(acc[i][2 * jj + 1], lo, hi);
            ob[(size_t)(c + 2) * N_ + 32 * i] = lo;
            ob[(size_t)(c + 3) * N_ + 32 * i] = hi;
        }
}

// ---------------- launch ------------------------------------------------------
extern "C" void kernel_launch(void* const* d_in, const int* in_sizes, int n_in,
                              void* d_out, int out_size)
{
    const float* x     = (const float*)d_in[0];
    const float* x1    = (const float*)d_in[1];
    const float* Wq    = (const float*)d_in[2];
    const float* bq    = (const float*)d_in[3];
    const float* Wk    = (const float*)d_in[4];
    const float* bk    = (const float*)d_in[5];
    const float* Wv    = (const float*)d_in[6];
    const float* bv    = (const float*)d_in[7];
    const float* gamma = (const float*)d_in[8];
    float* out = (float*)d_out;

    static int inited = 0;
    if (!inited) {
        cudaFuncSetAttribute(k_qk,    cudaFuncAttributeMaxDynamicSharedMemorySize, 73728);
        cudaFuncSetAttribute(k_small, cudaFuncAttributeMaxDynamicSharedMemorySize, 50080);
        cudaFuncSetAttribute(k_out,   cudaFuncAttributeMaxDynamicSharedMemorySize, 21648);
        inited = 1;
    }

    k_qk   <<<1024, 256, 73728>>>(x1, Wq, bq, Wk, bk);
    k_gmat <<<512, 256>>>(x);
    k_small<<<48, 128, 50080>>>(Wv, bv);
    k_out  <<<4096, 256, 21648>>>(gamma, out);
}